// round 1
// baseline (speedup 1.0000x reference)
#include <cuda_runtime.h>
#include <math.h>

// Problem constants
#define NB   8
#define NC   512
#define NL   1024          // H*W = 32*32
#define NS   77
#define NCTX 768
#define NH   8
#define HD   64
#define NG   32
#define C3   (3*NC)
#define FF   (4*NC)        // 2048

// ---------------- scratch (device globals; no allocation allowed) -----------
__device__ float g_h1 [NB*NC*NL];          // groupnorm(x)
__device__ float g_hn [NB*NC*NL];          // groupnorm(h1)
__device__ float g_qkv[NB*C3*NL];          // qkv conv output
__device__ float g_sc [NB*NH*NL*NL];       // self-attn scores (268 MB)
__device__ float g_sao[NB*NC*NL];          // self-attn output (pre-proj)
__device__ float g_hc [NB*NC*NL];          // running hidden state
__device__ float g_q2 [NB*NC*NL];          // cross-attn Q
__device__ float g_k2 [NB*NC*NS];          // cross-attn K
__device__ float g_v2 [NB*NC*NS];          // cross-attn V
__device__ float g_s2 [NB*NH*NL*NS];       // cross-attn scores
__device__ float g_ca [NB*NC*NL];          // cross-attn output (pre-proj)
__device__ float g_f1 [NB*FF*NL];          // FFN hidden

// ---------------- GroupNorm ------------------------------------------------
// one block per (b, group); cpg = C/G = 16, n = cpg*L = 16384
__global__ void groupnorm_kernel(const float* __restrict__ x,
                                 const float* __restrict__ gamma,
                                 const float* __restrict__ beta,
                                 float* __restrict__ out)
{
    const int cpg = NC / NG;                // 16
    const int n   = cpg * NL;               // 16384
    int bg = blockIdx.x;                    // b*NG + g
    int g  = bg % NG;
    long long base = (long long)bg * n;
    const float* xp = x + base;

    float sum = 0.f, sq = 0.f;
    for (int i = threadIdx.x; i < n; i += blockDim.x) {
        float v = xp[i];
        sum += v; sq += v * v;
    }
    __shared__ float s1[256], s2[256];
    s1[threadIdx.x] = sum; s2[threadIdx.x] = sq;
    __syncthreads();
    for (int s = 128; s > 0; s >>= 1) {
        if (threadIdx.x < s) {
            s1[threadIdx.x] += s1[threadIdx.x + s];
            s2[threadIdx.x] += s2[threadIdx.x + s];
        }
        __syncthreads();
    }
    float mean = s1[0] / n;
    float var  = s2[0] / n - mean * mean;
    float rstd = rsqrtf(var + 1e-5f);

    for (int i = threadIdx.x; i < n; i += blockDim.x) {
        int c = g * cpg + i / NL;
        out[base + i] = (xp[i] - mean) * rstd * gamma[c] + beta[c];
    }
}

// ---------------- NN GEMM:  C[z] = A[M,K] * B[z][K,N] (+bias)(+epi) --------
// A: weights row-major, shared over batch. B,C row-major with ld = N.
// epi: 0 none, 1 gelu, 2 residual (+res[z])
__global__ void gemm_nn_kernel(const float* __restrict__ A,
                               const float* __restrict__ B,
                               float* __restrict__ C,
                               const float* __restrict__ bias,
                               const float* __restrict__ res,
                               int M, int N, int K,
                               long long sB, long long sC,
                               int epi)
{
    __shared__ float As[16][68];
    __shared__ float Bs[16][64];
    int z = blockIdx.z;
    const float* Bz = B + (long long)z * sB;
    float*       Cz = C + (long long)z * sC;
    const float* Rz = res ? res + (long long)z * sC : nullptr;
    int row0 = blockIdx.y * 64, col0 = blockIdx.x * 64;
    int tid = threadIdx.x;
    int tx = tid & 15, ty = tid >> 4;

    float acc[4][4] = {};
    for (int k0 = 0; k0 < K; k0 += 16) {
#pragma unroll
        for (int p = 0; p < 4; p++) {
            int idx = tid + p * 256;
            int m = idx >> 4, k = idx & 15;
            As[k][m] = A[(row0 + m) * K + k0 + k];
        }
#pragma unroll
        for (int p = 0; p < 4; p++) {
            int idx = tid + p * 256;
            int k = idx >> 6, n = idx & 63;
            Bs[k][n] = Bz[(long long)(k0 + k) * N + col0 + n];
        }
        __syncthreads();
#pragma unroll
        for (int k = 0; k < 16; k++) {
            float4 a = *(const float4*)&As[k][ty * 4];
            float4 b = *(const float4*)&Bs[k][tx * 4];
            acc[0][0] += a.x * b.x; acc[0][1] += a.x * b.y; acc[0][2] += a.x * b.z; acc[0][3] += a.x * b.w;
            acc[1][0] += a.y * b.x; acc[1][1] += a.y * b.y; acc[1][2] += a.y * b.z; acc[1][3] += a.y * b.w;
            acc[2][0] += a.z * b.x; acc[2][1] += a.z * b.y; acc[2][2] += a.z * b.z; acc[2][3] += a.z * b.w;
            acc[3][0] += a.w * b.x; acc[3][1] += a.w * b.y; acc[3][2] += a.w * b.z; acc[3][3] += a.w * b.w;
        }
        __syncthreads();
    }
#pragma unroll
    for (int i = 0; i < 4; i++) {
        int r = row0 + ty * 4 + i;
        float bv = bias ? bias[r] : 0.f;
#pragma unroll
        for (int j = 0; j < 4; j++) {
            int c = col0 + tx * 4 + j;
            float v = acc[i][j] + bv;
            if (epi == 1) v = 0.5f * v * (1.0f + erff(v * 0.70710678118654752f));
            if (epi == 2) v += Rz[(long long)r * N + c];
            Cz[(long long)r * N + c] = v;
        }
    }
}

// ---------------- attention scores:  S[i,j] = scale * sum_d Q[d,i]*K[d,j] --
// per z = b*nh + h. d-dim fixed at HD=64, fully in smem (one load stage).
__global__ void attn_scores_kernel(const float* __restrict__ Q,
                                   const float* __restrict__ Kt,
                                   float* __restrict__ S,
                                   int ldq, int ldk, int Mi, int Nj,
                                   long long qSb, long long qSh,
                                   long long kSb, long long kSh,
                                   long long sSz, float scale)
{
    __shared__ float Qs[64][68];
    __shared__ float Ks[64][68];
    int z = blockIdx.z, b = z / NH, h = z % NH;
    const float* q = Q  + b * qSb + h * qSh;
    const float* kk = Kt + b * kSb + h * kSh;
    float* s = S + (long long)z * sSz;
    int i0 = blockIdx.y * 64, j0 = blockIdx.x * 64;
    int tid = threadIdx.x, tx = tid & 15, ty = tid >> 4;

#pragma unroll
    for (int p = 0; p < 16; p++) {
        int idx = tid + p * 256;
        int d = idx >> 6, c = idx & 63;
        Qs[d][c] = (i0 + c < Mi) ? q[(long long)d * ldq + i0 + c] : 0.f;
        Ks[d][c] = (j0 + c < Nj) ? kk[(long long)d * ldk + j0 + c] : 0.f;
    }
    __syncthreads();

    float acc[4][4] = {};
#pragma unroll 16
    for (int d = 0; d < 64; d++) {
        float4 a = *(const float4*)&Qs[d][ty * 4];
        float4 b = *(const float4*)&Ks[d][tx * 4];
        acc[0][0] += a.x * b.x; acc[0][1] += a.x * b.y; acc[0][2] += a.x * b.z; acc[0][3] += a.x * b.w;
        acc[1][0] += a.y * b.x; acc[1][1] += a.y * b.y; acc[1][2] += a.y * b.z; acc[1][3] += a.y * b.w;
        acc[2][0] += a.z * b.x; acc[2][1] += a.z * b.y; acc[2][2] += a.z * b.z; acc[2][3] += a.z * b.w;
        acc[3][0] += a.w * b.x; acc[3][1] += a.w * b.y; acc[3][2] += a.w * b.z; acc[3][3] += a.w * b.w;
    }
#pragma unroll
    for (int i = 0; i < 4; i++) {
        int r = i0 + ty * 4 + i;
        if (r >= Mi) continue;
#pragma unroll
        for (int j = 0; j < 4; j++) {
            int c = j0 + tx * 4 + j;
            if (c < Nj) s[(long long)r * Nj + c] = acc[i][j] * scale;
        }
    }
}

// ---------------- NT GEMM:  C[m,n] = sum_k A[m,k]*B[n,k] (+bias) -----------
// A ld = lda (K-contiguous rows), B ld = ldb (K-contiguous rows), C ld = ldc.
// per z = b*nh + h with separate b/h strides for each operand.
__global__ void gemm_nt_kernel(const float* __restrict__ A, int lda,
                               const float* __restrict__ B, int ldb,
                               float* __restrict__ C, int ldc,
                               const float* __restrict__ bias,
                               int M, int N, int K, int nh,
                               long long aSb, long long aSh,
                               long long bSb, long long bSh,
                               long long cSb, long long cSh)
{
    __shared__ float As[64][33];
    __shared__ float Bs[64][33];
    int z = blockIdx.z, b_ = z / nh, h_ = z % nh;
    const float* Az = A + b_ * aSb + h_ * aSh;
    const float* Bz = B + b_ * bSb + h_ * bSh;
    float*       Cz = C + b_ * cSb + h_ * cSh;
    int m0 = blockIdx.y * 64, n0 = blockIdx.x * 64;
    int tid = threadIdx.x, tx = tid & 15, ty = tid >> 4;

    float acc[4][4] = {};
    for (int k0 = 0; k0 < K; k0 += 32) {
#pragma unroll
        for (int p = 0; p < 8; p++) {
            int idx = tid + p * 256;
            int r = idx >> 5, kk = idx & 31;
            As[r][kk] = (m0 + r < M && k0 + kk < K)
                      ? Az[(long long)(m0 + r) * lda + k0 + kk] : 0.f;
            Bs[r][kk] = (n0 + r < N && k0 + kk < K)
                      ? Bz[(long long)(n0 + r) * ldb + k0 + kk] : 0.f;
        }
        __syncthreads();
#pragma unroll
        for (int kk = 0; kk < 32; kk++) {
            float a0 = As[ty * 4 + 0][kk], a1 = As[ty * 4 + 1][kk];
            float a2 = As[ty * 4 + 2][kk], a3 = As[ty * 4 + 3][kk];
            float b0 = Bs[tx * 4 + 0][kk], b1 = Bs[tx * 4 + 1][kk];
            float b2 = Bs[tx * 4 + 2][kk], b3 = Bs[tx * 4 + 3][kk];
            acc[0][0] += a0 * b0; acc[0][1] += a0 * b1; acc[0][2] += a0 * b2; acc[0][3] += a0 * b3;
            acc[1][0] += a1 * b0; acc[1][1] += a1 * b1; acc[1][2] += a1 * b2; acc[1][3] += a1 * b3;
            acc[2][0] += a2 * b0; acc[2][1] += a2 * b1; acc[2][2] += a2 * b2; acc[2][3] += a2 * b3;
            acc[3][0] += a3 * b0; acc[3][1] += a3 * b1; acc[3][2] += a3 * b2; acc[3][3] += a3 * b3;
        }
        __syncthreads();
    }
#pragma unroll
    for (int i = 0; i < 4; i++) {
        int r = m0 + ty * 4 + i;
        if (r >= M) continue;
        float bv = bias ? bias[r] : 0.f;
#pragma unroll
        for (int j = 0; j < 4; j++) {
            int c = n0 + tx * 4 + j;
            if (c < N) Cz[(long long)r * ldc + c] = acc[i][j] + bv;
        }
    }
}

// ---------------- row softmax (in place) ------------------------------------
__global__ void softmax_kernel(float* __restrict__ S, int N)
{
    long long row = blockIdx.x;
    float* p = S + row * N;
    int tid = threadIdx.x;
    __shared__ float red[128];

    float m = -1e30f;
    for (int j = tid; j < N; j += 128) m = fmaxf(m, p[j]);
    red[tid] = m; __syncthreads();
    for (int s = 64; s > 0; s >>= 1) {
        if (tid < s) red[tid] = fmaxf(red[tid], red[tid + s]);
        __syncthreads();
    }
    m = red[0]; __syncthreads();

    float sum = 0.f;
    for (int j = tid; j < N; j += 128) {
        float e = __expf(p[j] - m);
        p[j] = e; sum += e;
    }
    red[tid] = sum; __syncthreads();
    for (int s = 64; s > 0; s >>= 1) {
        if (tid < s) red[tid] += red[tid + s];
        __syncthreads();
    }
    float inv = 1.0f / red[0];
    for (int j = tid; j < N; j += 128) p[j] *= inv;
}

// ---------------- final residual add ----------------------------------------
__global__ void add_kernel(const float* __restrict__ a,
                           const float* __restrict__ b,
                           float* __restrict__ out, int n)
{
    int i = blockIdx.x * blockDim.x + threadIdx.x;
    if (i < n) out[i] = a[i] + b[i];
}

// ---------------- launch ----------------------------------------------------
extern "C" void kernel_launch(void* const* d_in, const int* in_sizes, int n_in,
                              void* d_out, int out_size)
{
    const float* x        = (const float*)d_in[0];
    const float* context  = (const float*)d_in[1];
    const float* gn_in_g  = (const float*)d_in[2];
    const float* gn_in_b  = (const float*)d_in[3];
    const float* sa_gn_g  = (const float*)d_in[4];
    const float* sa_gn_b  = (const float*)d_in[5];
    const float* qkv_w    = (const float*)d_in[6];
    const float* qkv_b    = (const float*)d_in[7];
    const float* sa_pw    = (const float*)d_in[8];
    const float* sa_pb    = (const float*)d_in[9];
    const float* q_w      = (const float*)d_in[10];
    const float* q_b      = (const float*)d_in[11];
    const float* k_w      = (const float*)d_in[12];
    const float* k_b      = (const float*)d_in[13];
    const float* v_w      = (const float*)d_in[14];
    const float* v_b      = (const float*)d_in[15];
    const float* ca_pw    = (const float*)d_in[16];
    const float* ca_pb    = (const float*)d_in[17];
    const float* w1       = (const float*)d_in[18];
    const float* b1       = (const float*)d_in[19];
    const float* w2       = (const float*)d_in[20];
    const float* b2       = (const float*)d_in[21];
    float* out = (float*)d_out;

    float *h1, *hn, *qkv, *sc, *sao, *hc, *q2, *k2, *v2, *s2, *ca, *f1;
    cudaGetSymbolAddress((void**)&h1,  g_h1);
    cudaGetSymbolAddress((void**)&hn,  g_hn);
    cudaGetSymbolAddress((void**)&qkv, g_qkv);
    cudaGetSymbolAddress((void**)&sc,  g_sc);
    cudaGetSymbolAddress((void**)&sao, g_sao);
    cudaGetSymbolAddress((void**)&hc,  g_hc);
    cudaGetSymbolAddress((void**)&q2,  g_q2);
    cudaGetSymbolAddress((void**)&k2,  g_k2);
    cudaGetSymbolAddress((void**)&v2,  g_v2);
    cudaGetSymbolAddress((void**)&s2,  g_s2);
    cudaGetSymbolAddress((void**)&ca,  g_ca);
    cudaGetSymbolAddress((void**)&f1,  g_f1);

    const float scale = 0.125f;                 // hd^-0.5, hd=64
    const long long CL = (long long)NC * NL;    // 512*1024
    const long long C3L = (long long)C3 * NL;

    // 1) h1 = GN(x; gn_in)
    groupnorm_kernel<<<NB * NG, 256>>>(x, gn_in_g, gn_in_b, h1);
    // 2) hn = GN(h1; sa_gn)
    groupnorm_kernel<<<NB * NG, 256>>>(h1, sa_gn_g, sa_gn_b, hn);
    // 3) qkv = qkv_w * hn + qkv_b    [1536,512]x[512,1024] per b
    gemm_nn_kernel<<<dim3(NL/64, C3/64, NB), 256>>>(
        qkv_w, hn, qkv, qkv_b, nullptr, C3, NL, NC, CL, C3L, 0);
    // 4) self-attn scores: S = scale * Q^T K  (per z = b*8+h)
    attn_scores_kernel<<<dim3(NL/64, NL/64, NB*NH), 256>>>(
        qkv,                    /* Q base */
        qkv + (long long)NC*NL, /* K base */
        sc, NL, NL, NL, NL,
        C3L, (long long)HD*NL,  /* q strides */
        C3L, (long long)HD*NL,  /* k strides */
        (long long)NL*NL, scale);
    // 5) softmax over rows of length 1024
    softmax_kernel<<<NB*NH*NL, 128>>>(sc, NL);
    // 6) sao[d,i] = sum_j V[d,j] P[i,j]
    gemm_nt_kernel<<<dim3(NL/64, 1, NB*NH), 256>>>(
        qkv + 2*(long long)NC*NL, NL,
        sc, NL, sao, NL, nullptr,
        HD, NL, NL, NH,
        C3L, (long long)HD*NL,
        (long long)NH*NL*NL, (long long)NL*NL,
        CL, (long long)HD*NL);
    // 7) hc = sa_proj * sao + bias + h1
    gemm_nn_kernel<<<dim3(NL/64, NC/64, NB), 256>>>(
        sa_pw, sao, hc, sa_pb, h1, NC, NL, NC, CL, CL, 2);
    // 8) q2 = q_w * hc + q_b
    gemm_nn_kernel<<<dim3(NL/64, NC/64, NB), 256>>>(
        q_w, hc, q2, q_b, nullptr, NC, NL, NC, CL, CL, 0);
    // 9/10) k2,v2 = w * context^T + b   [512,768]x[768,77] per b (NT)
    gemm_nt_kernel<<<dim3(2, NC/64, NB), 256>>>(
        k_w, NCTX, context, NCTX, k2, NS, k_b,
        NC, NS, NCTX, 1,
        0, 0, (long long)NS*NCTX, 0, (long long)NC*NS, 0);
    gemm_nt_kernel<<<dim3(2, NC/64, NB), 256>>>(
        v_w, NCTX, context, NCTX, v2, NS, v_b,
        NC, NS, NCTX, 1,
        0, 0, (long long)NS*NCTX, 0, (long long)NC*NS, 0);
    // 11) cross scores [1024 x 77]
    attn_scores_kernel<<<dim3(2, NL/64, NB*NH), 256>>>(
        q2, k2, s2, NL, NS, NL, NS,
        CL, (long long)HD*NL,
        (long long)NC*NS, (long long)HD*NS,
        (long long)NL*NS, scale);
    // 12) softmax rows of length 77
    softmax_kernel<<<NB*NH*NL, 128>>>(s2, NS);
    // 13) ca[d,i] = sum_s V2[d,s] P2[i,s]
    gemm_nt_kernel<<<dim3(NL/64, 1, NB*NH), 256>>>(
        v2, NS, s2, NS, ca, NL, nullptr,
        HD, NL, NS, NH,
        (long long)NC*NS, (long long)HD*NS,
        (long long)NH*NL*NS, (long long)NL*NS,
        CL, (long long)HD*NL);
    // 14) hc = ca_proj * ca + bias + hc
    gemm_nn_kernel<<<dim3(NL/64, NC/64, NB), 256>>>(
        ca_pw, ca, hc, ca_pb, hc, NC, NL, NC, CL, CL, 2);
    // 15) f1 = gelu(w1 * hc + b1)   [2048,512]
    gemm_nn_kernel<<<dim3(NL/64, FF/64, NB), 256>>>(
        w1, hc, f1, b1, nullptr, FF, NL, NC, CL, (long long)FF*NL, 1);
    // 16) hc = w2 * f1 + b2 + hc    [512,2048]
    gemm_nn_kernel<<<dim3(NL/64, NC/64, NB), 256>>>(
        w2, f1, hc, b2, hc, NC, NL, FF, (long long)FF*NL, CL, 2);
    // 17) out = x + hc
    int n = NB * NC * NL;
    add_kernel<<<(n + 1023) / 1024, 1024>>>(x, hc, out, n);
}